// round 4
// baseline (speedup 1.0000x reference)
#include <cuda_runtime.h>

#define B    4
#define CIN  3
#define COUT 16
#define H    256
#define W    256
#define K    5
#define PAD  2

typedef unsigned long long u64;

__device__ float g_mid[B * COUT * H * W];   // 16 MB intermediate

// ---- packed f32x2 add (Blackwell sm_103a); min/max.f32x2 do NOT exist -----
union F2U { float2 f; u64 u; };

__device__ __forceinline__ float2 addx2(float2 a, float2 b) {
    F2U A, Bu, R;
    A.f = a; Bu.f = b;
    asm("add.rn.f32x2 %0, %1, %2;" : "=l"(R.u) : "l"(A.u), "l"(Bu.u));
    return R.f;
}

// ---------------------------------------------------------------------------
// Dilation: out_d[b,o,i,j] = sum_c max_t( x[clamped window] + w_d[o,c,t] )
// Tile 32x16, 2 rows/thread, packed row-pair adds + scalar FMNMX.
// ---------------------------------------------------------------------------
#define DT_W 32
#define DT_H 16

__global__ __launch_bounds__(256) void dilate_kernel(const float* __restrict__ x,
                                                     const float* __restrict__ wd) {
    __shared__ float  xs[CIN][DT_H + 4][DT_W + 4];      // scalar tile + halo
    __shared__ float2 ws2[COUT * CIN * K * K];          // {w, w} replicated

    const int b      = blockIdx.z;
    const int tile_y = blockIdx.y * DT_H;
    const int tile_x = blockIdx.x * DT_W;
    const int tid    = threadIdx.y * 32 + threadIdx.x;

    for (int i = tid; i < COUT * CIN * K * K; i += 256) {
        float w = wd[i];
        ws2[i] = make_float2(w, w);
    }

    const int XS_N = CIN * (DT_H + 4) * (DT_W + 4);
    for (int i = tid; i < XS_N; i += 256) {
        int c   = i / ((DT_H + 4) * (DT_W + 4));
        int rem = i % ((DT_H + 4) * (DT_W + 4));
        int r   = rem / (DT_W + 4);
        int col = rem % (DT_W + 4);
        int gi = min(max(tile_y + r - PAD, 0), H - 1);
        int gj = min(max(tile_x + col - PAD, 0), W - 1);
        xs[c][r][col] = x[((b * CIN + c) * H + gi) * W + gj];
    }
    __syncthreads();

    const int tx = threadIdx.x;
    const int ty = threadIdx.y;

    float acc0[COUT], acc1[COUT];
#pragma unroll
    for (int o = 0; o < COUT; o++) { acc0[o] = 0.0f; acc1[o] = 0.0f; }

#pragma unroll
    for (int c = 0; c < CIN; c++) {
        // Packed window: pw[t] = { x[row+di], x[row+di+1] } for tap t=(di,dj)
        float2 pw[K * K];
#pragma unroll
        for (int di = 0; di < K; di++)
#pragma unroll
            for (int dj = 0; dj < K; dj++) {
                pw[di * K + dj].x = xs[c][ty * 2 + di][tx + dj];
                pw[di * K + dj].y = xs[c][ty * 2 + di + 1][tx + dj];
            }

#pragma unroll
        for (int o = 0; o < COUT; o++) {
            const float2* w2 = &ws2[(o * CIN + c) * (K * K)];
            float2 s = addx2(pw[0], w2[0]);
            float m0 = s.x, m1 = s.y;
#pragma unroll
            for (int t = 1; t < K * K; t++) {
                s  = addx2(pw[t], w2[t]);
                m0 = fmaxf(m0, s.x);
                m1 = fmaxf(m1, s.y);
            }
            acc0[o] += m0;
            acc1[o] += m1;
        }
    }

    const int gi0 = tile_y + ty * 2;
    const int gj  = tile_x + tx;
#pragma unroll
    for (int o = 0; o < COUT; o++) {
        g_mid[((b * COUT + o) * H + gi0)     * W + gj] = acc0[o];
        g_mid[((b * COUT + o) * H + gi0 + 1) * W + gj] = acc1[o];
    }
}

// ---------------------------------------------------------------------------
// Erosion: out[b,o,i,j] = min_t( y[clamped window] - w_e[o,t] )
//        = min_t( y + (-w) )  -> packed adds with pre-negated weights.
// Tile 32x32, 4 rows/thread.
// ---------------------------------------------------------------------------
#define ET 32

__global__ __launch_bounds__(256) void erode_kernel(const float* __restrict__ we_g,
                                                    float* __restrict__ out) {
    __shared__ float  ys[ET + 4][ET + 4];
    __shared__ float2 we2[K * K];          // {-w, -w}

    const int bo     = blockIdx.z;
    const int o      = bo % COUT;
    const int tile_y = blockIdx.y * ET;
    const int tile_x = blockIdx.x * ET;
    const int tid    = threadIdx.y * 32 + threadIdx.x;

    if (tid < K * K) {
        float w = we_g[o * K * K + tid];
        we2[tid] = make_float2(-w, -w);
    }

    const float* y = g_mid + (size_t)bo * H * W;
    for (int i = tid; i < (ET + 4) * (ET + 4); i += 256) {
        int r   = i / (ET + 4);
        int col = i % (ET + 4);
        int gi = min(max(tile_y + r - PAD, 0), H - 1);
        int gj = min(max(tile_x + col - PAD, 0), W - 1);
        ys[r][col] = y[gi * W + gj];
    }
    __syncthreads();

    const int tx = threadIdx.x;
    const int ty = threadIdx.y;

    // Packed window pairs at bases 0..6: pw[i][dj] = { y[base+i], y[base+i+1] }
    float2 pw[7][K];
#pragma unroll
    for (int i = 0; i < 7; i++)
#pragma unroll
        for (int dj = 0; dj < K; dj++) {
            pw[i][dj].x = ys[ty * 4 + i][tx + dj];
            pw[i][dj].y = ys[ty * 4 + i + 1][tx + dj];
        }

    float m0 = 1e30f, m1 = 1e30f, m2 = 1e30f, m3 = 1e30f;

#pragma unroll
    for (int di = 0; di < K; di++) {
#pragma unroll
        for (int dj = 0; dj < K; dj++) {
            float2 w = we2[di * K + dj];
            float2 s01 = addx2(pw[di][dj],     w);
            float2 s23 = addx2(pw[di + 2][dj], w);
            m0 = fminf(m0, s01.x);
            m1 = fminf(m1, s01.y);
            m2 = fminf(m2, s23.x);
            m3 = fminf(m3, s23.y);
        }
    }

    const int gj = tile_x + tx;
    const int gi = tile_y + ty * 4;
    float* op = out + ((size_t)bo * H + gi) * W + gj;
    op[0]     = m0;
    op[W]     = m1;
    op[2 * W] = m2;
    op[3 * W] = m3;
}

// ---------------------------------------------------------------------------
extern "C" void kernel_launch(void* const* d_in, const int* in_sizes, int n_in,
                              void* d_out, int out_size) {
    const float* x  = (const float*)d_in[0];
    const float* wd = (const float*)d_in[1];
    const float* we = (const float*)d_in[2];
    float*       out = (float*)d_out;

    dim3 bD(32, 8);
    dim3 gD(W / DT_W, H / DT_H, B);        // 8 x 16 x 4
    dilate_kernel<<<gD, bD>>>(x, wd);

    dim3 bE(32, 8);
    dim3 gE(W / ET, H / ET, B * COUT);     // 8 x 8 x 64
    erode_kernel<<<gE, bE>>>(we, out);
}

// round 5
// speedup vs baseline: 1.4048x; 1.4048x over previous
#include <cuda_runtime.h>
#include <cuda_fp16.h>

#define B    4
#define CIN  3
#define COUT 16
#define H    256
#define W    256
#define K    5
#define PAD  2

__device__ float g_mid[B * COUT * H * W];   // 16 MB intermediate (fp32)

// ---------------------------------------------------------------------------
// Dilation: out_d[b,o,i,j] = sum_c max_t( x[clamped win] + w_d[o,c,t] )
// Tile 32x16, 2 rows/thread packed into half2 lanes. Accumulate in fp32.
// ---------------------------------------------------------------------------
#define DT_W 32
#define DT_H 16
#define XR (DT_H + 3)   // 19 row-pair rows
#define XC (DT_W + 4)   // 36 cols

__global__ __launch_bounds__(256) void dilate_kernel(const float* __restrict__ x,
                                                     const float* __restrict__ wd) {
    __shared__ __half2 xs2[CIN][XR][XC];        // {x[r], x[r+1]} row pairs, fp16
    __shared__ __half2 wsh[COUT * CIN * K * K]; // {w, w} replicated, fp16

    const int b      = blockIdx.z;
    const int tile_y = blockIdx.y * DT_H;
    const int tile_x = blockIdx.x * DT_W;
    const int tid    = threadIdx.y * 32 + threadIdx.x;

    for (int i = tid; i < COUT * CIN * K * K; i += 256)
        wsh[i] = __float2half2_rn(wd[i]);

    const int XN = CIN * XR * XC;
    for (int i = tid; i < XN; i += 256) {
        int c   = i / (XR * XC);
        int rem = i % (XR * XC);
        int r   = rem / XC;
        int col = rem % XC;
        int g0 = min(max(tile_y + r - PAD, 0), H - 1);
        int g1 = min(max(tile_y + r + 1 - PAD, 0), H - 1);
        int gj = min(max(tile_x + col - PAD, 0), W - 1);
        const float* xc = x + ((size_t)(b * CIN + c)) * H * W;
        xs2[c][r][col] = __floats2half2_rn(xc[g0 * W + gj], xc[g1 * W + gj]);
    }
    __syncthreads();

    const int tx = threadIdx.x;
    const int ty = threadIdx.y;

    float acc0[COUT], acc1[COUT];
#pragma unroll
    for (int o = 0; o < COUT; o++) { acc0[o] = 0.0f; acc1[o] = 0.0f; }

#pragma unroll
    for (int c = 0; c < CIN; c++) {
        // register window: 25 half2 row-pairs
        __half2 pv[K * K];
#pragma unroll
        for (int di = 0; di < K; di++)
#pragma unroll
            for (int dj = 0; dj < K; dj++)
                pv[di * K + dj] = xs2[c][ty * 2 + di][tx + dj];

#pragma unroll
        for (int o = 0; o < COUT; o++) {
            const __half2* w = &wsh[(o * CIN + c) * (K * K)];
            __half2 m = __hadd2(pv[0], w[0]);
#pragma unroll
            for (int t = 1; t < K * K; t++)
                m = __hmax2(m, __hadd2(pv[t], w[t]));
            float2 mf = __half22float2(m);
            acc0[o] += mf.x;
            acc1[o] += mf.y;
        }
    }

    const int gi0 = tile_y + ty * 2;
    const int gj  = tile_x + tx;
#pragma unroll
    for (int o = 0; o < COUT; o++) {
        g_mid[((b * COUT + o) * H + gi0)     * W + gj] = acc0[o];
        g_mid[((b * COUT + o) * H + gi0 + 1) * W + gj] = acc1[o];
    }
}

// ---------------------------------------------------------------------------
// Erosion (fp32, identical to the 21us R2 version).
// out[b,o,i,j] = min_t( y[clamped win] - w_e[o,t] ). Tile 32x32, 4 rows/thread.
// ---------------------------------------------------------------------------
#define ET 32

__global__ __launch_bounds__(256) void erode_kernel(const float* __restrict__ we_g,
                                                    float* __restrict__ out) {
    __shared__ float ys[ET + 4][ET + 4];
    __shared__ float we[K * K];

    const int bo     = blockIdx.z;               // b*COUT + o
    const int o      = bo % COUT;
    const int tile_y = blockIdx.y * ET;
    const int tile_x = blockIdx.x * ET;
    const int tid    = threadIdx.y * 32 + threadIdx.x;

    if (tid < K * K) we[tid] = we_g[o * K * K + tid];

    const float* y = g_mid + (size_t)bo * H * W;
    for (int i = tid; i < (ET + 4) * (ET + 4); i += 256) {
        int r   = i / (ET + 4);
        int col = i % (ET + 4);
        int gi = min(max(tile_y + r - PAD, 0), H - 1);
        int gj = min(max(tile_x + col - PAD, 0), W - 1);
        ys[r][col] = y[gi * W + gj];
    }
    __syncthreads();

    const int tx = threadIdx.x;
    const int ty = threadIdx.y;

    float yr[8][5];
#pragma unroll
    for (int ii = 0; ii < 8; ii++)
#pragma unroll
        for (int jj = 0; jj < 5; jj++)
            yr[ii][jj] = ys[ty * 4 + ii][tx + jj];

    float m[4];
#pragma unroll
    for (int p = 0; p < 4; p++) m[p] = 1e30f;

#pragma unroll
    for (int di = 0; di < K; di++) {
#pragma unroll
        for (int dj = 0; dj < K; dj++) {
            float w = we[di * K + dj];
#pragma unroll
            for (int p = 0; p < 4; p++)
                m[p] = fminf(m[p], yr[p + di][dj] - w);
        }
    }

    const int gj = tile_x + tx;
#pragma unroll
    for (int p = 0; p < 4; p++)
        out[((size_t)bo * H + tile_y + ty * 4 + p) * W + gj] = m[p];
}

// ---------------------------------------------------------------------------
extern "C" void kernel_launch(void* const* d_in, const int* in_sizes, int n_in,
                              void* d_out, int out_size) {
    const float* x  = (const float*)d_in[0];
    const float* wd = (const float*)d_in[1];
    const float* we = (const float*)d_in[2];
    float*       out = (float*)d_out;

    dim3 bD(32, 8);
    dim3 gD(W / DT_W, H / DT_H, B);        // 8 x 16 x 4
    dilate_kernel<<<gD, bD>>>(x, wd);

    dim3 bE(32, 8);
    dim3 gE(W / ET, H / ET, B * COUT);     // 8 x 8 x 64
    erode_kernel<<<gE, bE>>>(we, out);
}

// round 6
// speedup vs baseline: 1.4699x; 1.0463x over previous
#include <cuda_runtime.h>
#include <cuda_fp16.h>

#define B    4
#define CIN  3
#define COUT 16
#define H    256
#define W    256
#define K    5
#define PAD  2

// Intermediate (dilated) buffer in fp16: 4*16*256*256 halves = 8 MB.
__device__ __half g_midh[B * COUT * H * W];

// ---------------------------------------------------------------------------
// Dilation: out_d[b,o,i,j] = sum_c max_t( x[clamped win] + w_d[o,c,t] )
// Tile 32x16, 2 rows/thread packed into half2 lanes. Accumulate in fp32,
// store fp16.
// ---------------------------------------------------------------------------
#define DT_W 32
#define DT_H 16
#define XR (DT_H + 3)   // 19 row-pair rows
#define XC (DT_W + 4)   // 36 cols

__global__ __launch_bounds__(256) void dilate_kernel(const float* __restrict__ x,
                                                     const float* __restrict__ wd) {
    __shared__ __half2 xs2[CIN][XR][XC];        // {x[r], x[r+1]} row pairs
    __shared__ __half2 wsh[COUT * CIN * K * K]; // {w, w} replicated

    const int b      = blockIdx.z;
    const int tile_y = blockIdx.y * DT_H;
    const int tile_x = blockIdx.x * DT_W;
    const int tid    = threadIdx.y * 32 + threadIdx.x;

    for (int i = tid; i < COUT * CIN * K * K; i += 256)
        wsh[i] = __float2half2_rn(wd[i]);

    const int XN = CIN * XR * XC;
    for (int i = tid; i < XN; i += 256) {
        int c   = i / (XR * XC);
        int rem = i % (XR * XC);
        int r   = rem / XC;
        int col = rem % XC;
        int g0 = min(max(tile_y + r - PAD, 0), H - 1);
        int g1 = min(max(tile_y + r + 1 - PAD, 0), H - 1);
        int gj = min(max(tile_x + col - PAD, 0), W - 1);
        const float* xc = x + ((size_t)(b * CIN + c)) * H * W;
        xs2[c][r][col] = __floats2half2_rn(xc[g0 * W + gj], xc[g1 * W + gj]);
    }
    __syncthreads();

    const int tx = threadIdx.x;
    const int ty = threadIdx.y;

    float acc0[COUT], acc1[COUT];
#pragma unroll
    for (int o = 0; o < COUT; o++) { acc0[o] = 0.0f; acc1[o] = 0.0f; }

#pragma unroll
    for (int c = 0; c < CIN; c++) {
        __half2 pv[K * K];
#pragma unroll
        for (int di = 0; di < K; di++)
#pragma unroll
            for (int dj = 0; dj < K; dj++)
                pv[di * K + dj] = xs2[c][ty * 2 + di][tx + dj];

#pragma unroll
        for (int o = 0; o < COUT; o++) {
            const __half2* w = &wsh[(o * CIN + c) * (K * K)];
            __half2 m = __hadd2(pv[0], w[0]);
#pragma unroll
            for (int t = 1; t < K * K; t++)
                m = __hmax2(m, __hadd2(pv[t], w[t]));
            float2 mf = __half22float2(m);
            acc0[o] += mf.x;
            acc1[o] += mf.y;
        }
    }

    const int gi0 = tile_y + ty * 2;
    const int gj  = tile_x + tx;
#pragma unroll
    for (int o = 0; o < COUT; o++) {
        g_midh[((b * COUT + o) * H + gi0)     * W + gj] = __float2half(acc0[o]);
        g_midh[((b * COUT + o) * H + gi0 + 1) * W + gj] = __float2half(acc1[o]);
    }
}

// ---------------------------------------------------------------------------
// Erosion: out[b,o,i,j] = min_t( y[clamped win] - w_e[o,t] )
//        = min_t( y + (-w) ), fp16 packed: 4 rows/thread as 2 half2 accums.
// Tile 32x32. smem holds row-pairs at EVERY offset: ysp[p] = rows
// (tile_y+p-2, tile_y+p-1).
// ---------------------------------------------------------------------------
#define ET 32
#define YP_R (ET + 3)    // 35 pair rows
#define YP_C (ET + 4)    // 36 cols

__global__ __launch_bounds__(256) void erode_kernel(const float* __restrict__ we_g,
                                                    float* __restrict__ out) {
    __shared__ __half2 ysp[YP_R][YP_C];
    __shared__ __half2 we2[K * K];          // {-w, -w}

    const int bo     = blockIdx.z;               // b*COUT + o
    const int o      = bo % COUT;
    const int tile_y = blockIdx.y * ET;
    const int tile_x = blockIdx.x * ET;
    const int tid    = threadIdx.y * 32 + threadIdx.x;

    if (tid < K * K) {
        float w = we_g[o * K * K + tid];
        we2[tid] = __float2half2_rn(-w);
    }

    const __half* y = g_midh + (size_t)bo * H * W;
    for (int i = tid; i < YP_R * YP_C; i += 256) {
        int p   = i / YP_C;
        int col = i % YP_C;
        int g0 = min(max(tile_y + p - 2, 0), H - 1);
        int g1 = min(max(tile_y + p - 1, 0), H - 1);
        int gj = min(max(tile_x + col - 2, 0), W - 1);
        ysp[p][col] = __halves2half2(y[g0 * W + gj], y[g1 * W + gj]);
    }
    __syncthreads();

    const int tx = threadIdx.x;
    const int ty = threadIdx.y;

    // Window pairs: pv[p][dj], p = 0..6 relative pair offset
    __half2 pv[7][K];
#pragma unroll
    for (int p = 0; p < 7; p++)
#pragma unroll
        for (int dj = 0; dj < K; dj++)
            pv[p][dj] = ysp[ty * 4 + p][tx + dj];

    // Seed with tap 0
    __half2 m0 = __hadd2(pv[0][0], we2[0]);   // output rows l, l+1
    __half2 m1 = __hadd2(pv[2][0], we2[0]);   // output rows l+2, l+3

#pragma unroll
    for (int t = 1; t < K * K; t++) {
        const int di = t / K, dj = t % K;
        __half2 w = we2[t];
        m0 = __hmin2(m0, __hadd2(pv[di][dj],     w));
        m1 = __hmin2(m1, __hadd2(pv[di + 2][dj], w));
    }

    const int gj = tile_x + tx;
    const int gi = tile_y + ty * 4;
    float2 r01 = __half22float2(m0);
    float2 r23 = __half22float2(m1);
    float* op = out + ((size_t)bo * H + gi) * W + gj;
    op[0]     = r01.x;
    op[W]     = r01.y;
    op[2 * W] = r23.x;
    op[3 * W] = r23.y;
}

// ---------------------------------------------------------------------------
extern "C" void kernel_launch(void* const* d_in, const int* in_sizes, int n_in,
                              void* d_out, int out_size) {
    const float* x  = (const float*)d_in[0];
    const float* wd = (const float*)d_in[1];
    const float* we = (const float*)d_in[2];
    float*       out = (float*)d_out;

    dim3 bD(32, 8);
    dim3 gD(W / DT_W, H / DT_H, B);        // 8 x 16 x 4
    dilate_kernel<<<gD, bD>>>(x, wd);

    dim3 bE(32, 8);
    dim3 gE(W / ET, H / ET, B * COUT);     // 8 x 8 x 64
    erode_kernel<<<gE, bE>>>(we, out);
}